// round 16
// baseline (speedup 1.0000x reference)
#include <cuda_runtime.h>
#include <math.h>

#define N_RAYS   262144
#define HIDDEN   256
#define MAX_ITERS 32
#define FAR_DIST 6.0f
#define HIT_T    1e-5f
#define PERT     1e-3f
#define THREADS  128
#define RPT      2
#define NBKT     256
#define NBLK     (N_RAYS / 256)             // 1024 key blocks
#define NWARPS_TOT (N_RAYS / (32 * RPT))    // 4096 trace warps
#define SKIP_BKT 255
#define KILL_MARGIN 2.5e-3f                 // > PERT + HIT_T + fp slop

typedef unsigned long long u64;

// ---- packed f32x2 helpers (sm_103a) ----
__device__ __forceinline__ u64 ffma2(u64 a, u64 b, u64 c) {
    u64 d;
    asm("fma.rn.f32x2 %0, %1, %2, %3;" : "=l"(d) : "l"(a), "l"(b), "l"(c));
    return d;
}
__device__ __forceinline__ u64 fadd2(u64 a, u64 b) {
    u64 d;
    asm("add.rn.f32x2 %0, %1, %2;" : "=l"(d) : "l"(a), "l"(b));
    return d;
}
__device__ __forceinline__ u64 pack2(float lo, float hi) {
    u64 r;
    asm("mov.b64 %0, {%1, %2};" : "=l"(r) : "f"(lo), "f"(hi));
    return r;
}
__device__ __forceinline__ float2 unpack2(u64 v) {
    float2 r;
    asm("mov.b64 {%0, %1}, %2;" : "=f"(r.x), "=f"(r.y) : "l"(v));
    return r;
}
__device__ __forceinline__ u64 relu2(u64 h) {
    float2 f = unpack2(h);
    return pack2(fmaxf(f.x, 0.0f), fmaxf(f.y, 0.0f));
}
// packed |.|: clear both sign bits
__device__ __forceinline__ u64 abs2(u64 h) {
    return h & 0x7FFFFFFF7FFFFFFFULL;
}
// tanh with ~1e-6 abs error (damped x1e-3 -> ~1e-9 in d)
__device__ __forceinline__ float tanh_fast(float x) {
    const float e = __expf(2.0f * x);
    return 1.0f - __fdividef(2.0f, e + 1.0f);
}

// ---- sorting scratch + precomputed u,v (allocation-free: device globals) ----
__device__ int g_bucket[N_RAYS];
__device__ int g_perm[N_RAYS];
__device__ int g_blockhist[NBLK * NBKT];
__device__ int g_blockbase[NBKT * NBLK];
__device__ int g_tot[NBKT];
__device__ int g_bucketbase[NBKT];
__device__ float4 g_uv;   // u = 0.5*sum q_i w_i (xyz), v = 0.5*sum q_i b_i (w)

// ---- Phase 1: cheap analytic proxy key (R13 proved exact keys buy nothing)
// ----          + conservative provably-never-hit skip flag.
__global__ void key_blockhist_kernel(const float* __restrict__ origins,
                                     const float* __restrict__ directions,
                                     const float* __restrict__ center,
                                     const float* __restrict__ radius)
{
    __shared__ int s_hist[NBKT];
    const int t = threadIdx.x;
    s_hist[t] = 0;
    __syncthreads();

    const int r = blockIdx.x * 256 + t;
    const float ox = origins[3 * r + 0] - center[0];
    const float oy = origins[3 * r + 1] - center[1];
    const float oz = origins[3 * r + 2] - center[2];
    const float dx = directions[3 * r + 0];
    const float dy = directions[3 * r + 1];
    const float dz = directions[3 * r + 2];
    const float rad = radius[0];

    // tca = dot(o-c,d); forward closest approach iff tca<0 (t* = -tca > 0).
    const float tca = ox * dx + oy * dy + oz * dz;
    const float oc2 = ox * ox + oy * oy + oz * oz;
    const float b   = sqrtf(fmaxf(oc2 - tca * tca, 0.0f));
    const float minD = (tca < 0.0f) ? b : sqrtf(oc2);
    const bool skip = (minD - rad) > 2e-3f;

    int bkt;
    if (skip) {
        bkt = SKIP_BKT;
    } else {
        // proxy difficulty key: grazing margin, compressed fine near zero
        const float key = fabsf(b - rad);
        const float u   = key / (key + 0.05f);
        bkt = min(126, (int)(u * 127.0f));
        if (b >= rad) bkt += 127;            // hit side 0..126, miss side 127..253
    }
    g_bucket[r] = bkt;
    atomicAdd(&s_hist[bkt], 1);
    __syncthreads();
    g_blockhist[blockIdx.x * NBKT + t] = s_hist[t];
}

__global__ void bucket_scan_kernel()
{
    __shared__ int s[NBLK];
    const int bucket = blockIdx.x;
    const int t = threadIdx.x;
    const int c = g_blockhist[t * NBKT + bucket];
    s[t] = c;
    __syncthreads();
    #pragma unroll
    for (int off = 1; off < NBLK; off <<= 1) {
        const int v = (t >= off) ? s[t - off] : 0;
        __syncthreads();
        s[t] += v;
        __syncthreads();
    }
    g_blockbase[bucket * NBLK + t] = s[t] - c;
    if (t == NBLK - 1) g_tot[bucket] = s[t];
}

// Phase 3: scan of bucket totals + deterministic u,v reduction.
__global__ void total_scan_kernel(const float* __restrict__ W1,
                                  const float* __restrict__ b1,
                                  const float* __restrict__ W2)
{
    __shared__ int s[NBKT];
    __shared__ float4 red[NBKT];
    const int t = threadIdx.x;
    const int h = g_tot[t];
    s[t] = h;
    const float qh = 0.5f * W2[t];
    red[t] = make_float4(qh * W1[t], qh * W1[HIDDEN + t],
                         qh * W1[2 * HIDDEN + t], qh * b1[t]);
    __syncthreads();
    #pragma unroll
    for (int off = 1; off < NBKT; off <<= 1) {
        const int v = (t >= off) ? s[t - off] : 0;
        __syncthreads();
        s[t] += v;
        __syncthreads();
    }
    g_bucketbase[t] = s[t] - h;
    #pragma unroll
    for (int off = NBKT / 2; off >= 1; off >>= 1) {
        if (t < off) {
            float4 a = red[t], bb = red[t + off];
            red[t] = make_float4(a.x + bb.x, a.y + bb.y, a.z + bb.z, a.w + bb.w);
        }
        __syncthreads();
    }
    if (t == 0) g_uv = red[0];
}

__global__ void scatter_kernel()
{
    __shared__ int s_base[NBKT];
    __shared__ int s_cnt[NBKT];
    const int t = threadIdx.x;
    s_base[t] = g_bucketbase[t] + g_blockbase[t * NBLK + blockIdx.x];
    s_cnt[t] = 0;
    __syncthreads();
    const int r = blockIdx.x * 256 + t;
    const int bkt = g_bucket[r];
    const int lr = atomicAdd(&s_cnt[bkt], 1);
    g_perm[s_base[bkt] + lr] = r;
}

// ---- main trace kernel: unit-pair packed f32x2 MLP, relu-free layer 2 ----
__global__ __launch_bounds__(THREADS)
void sphere_trace_render_kernel(const float* __restrict__ origins,
                                const float* __restrict__ directions,
                                const float* __restrict__ center,
                                const float* __restrict__ radius,
                                const float* __restrict__ W1,
                                const float* __restrict__ b1,
                                const float* __restrict__ W2,
                                const float* __restrict__ b2,
                                const float* __restrict__ Wc1,
                                const float* __restrict__ bc1,
                                const float* __restrict__ Wc2,
                                const float* __restrict__ bc2,
                                float* __restrict__ out)
{
    // Pair-packed weights: pair j = units (2j, 2j+1).
    __shared__ ulonglong2 sW1v[HIDDEN];
    __shared__ u64        sQv[HIDDEN / 2];     // (q_e/2, q_o/2)
    __shared__ ulonglong2 sC1v[HIDDEN];
    __shared__ ulonglong2 sC2xy[HIDDEN / 2];
    __shared__ u64        sC2z[HIDDEN / 2];

    const int t = threadIdx.x;
    for (int i = t; i < HIDDEN; i += THREADS) {
        const int j = i >> 1;
        float4 v;
        if ((i & 1) == 0)
            v = make_float4(W1[2 * j], W1[2 * j + 1], W1[HIDDEN + 2 * j], W1[HIDDEN + 2 * j + 1]);
        else
            v = make_float4(W1[2 * HIDDEN + 2 * j], W1[2 * HIDDEN + 2 * j + 1], b1[2 * j], b1[2 * j + 1]);
        ((float4*)sW1v)[i] = v;
        if ((i & 1) == 0)
            v = make_float4(Wc1[2 * j], Wc1[2 * j + 1], Wc1[HIDDEN + 2 * j], Wc1[HIDDEN + 2 * j + 1]);
        else
            v = make_float4(Wc1[2 * HIDDEN + 2 * j], Wc1[2 * HIDDEN + 2 * j + 1], bc1[2 * j], bc1[2 * j + 1]);
        ((float4*)sC1v)[i] = v;
    }
    for (int i = t; i < HIDDEN / 2; i += THREADS) {
        ((float2*)sQv)[i] = make_float2(0.5f * W2[2 * i], 0.5f * W2[2 * i + 1]);
        ((float4*)sC2xy)[i] = make_float4(Wc2[3 * (2 * i)],     Wc2[3 * (2 * i + 1)],
                                          Wc2[3 * (2 * i) + 1], Wc2[3 * (2 * i + 1) + 1]);
        ((float2*)sC2z)[i]  = make_float2(Wc2[3 * (2 * i) + 2], Wc2[3 * (2 * i + 1) + 2]);
    }
    __syncthreads();

    // Warp -> sorted segment, hard/easy folded for SM load balance.
    const int w = t >> 5, lane = t & 31;
    const int g = blockIdx.x * (THREADS / 32) + w;                 // 0..4095
    const int s = (g & 1) ? (NWARPS_TOT - 1 - (g >> 1)) : (g >> 1);
    const int base = s * (32 * RPT) + lane;

    const int rayA = g_perm[base];
    const int rayB = g_perm[base + 32];

    float pxA = origins[3 * rayA + 0], pyA = origins[3 * rayA + 1], pzA = origins[3 * rayA + 2];
    float pxB = origins[3 * rayB + 0], pyB = origins[3 * rayB + 1], pzB = origins[3 * rayB + 2];
    const float dxA = directions[3 * rayA + 0], dyA = directions[3 * rayA + 1], dzA = directions[3 * rayA + 2];
    const float dxB = directions[3 * rayB + 0], dyB = directions[3 * rayB + 1], dzB = directions[3 * rayB + 2];

    const float cx  = center[0];
    const float cy  = center[1];
    const float cz  = center[2];
    const float rad = radius[0];
    const float bb2 = b2[0];
    const float bo0 = bc2[0];
    const float bo1 = bc2[1];
    const float bo2 = bc2[2];
    const float4 uv = g_uv;     // u (xyz), v (w): linear half of relu split

    float distA = 0.0f, distB = 0.0f;
    bool  unfA = (g_bucket[rayA] != SKIP_BKT);
    bool  unfB = (g_bucket[rayB] != SKIP_BKT);
    bool  hitA = false, hitB = false;

    for (int it = 0; it < MAX_ITERS; ++it) {
        if (__all_sync(0xFFFFFFFFu, !unfA && !unfB)) break;

        // ---- Geometry (FROZEN form): norm = fma(rz,rz, fma(rx,rx, ry*ry))
        const float rxA = pxA - cx, ryA = pyA - cy, rzA = pzA - cz;
        const float baseA = sqrtf(fmaf(rzA, rzA, fmaf(rxA, rxA, __fmul_rn(ryA, ryA)))) - rad;
        const float rxB = pxB - cx, ryB = pyB - cy, rzB = pzB - cz;
        const float baseB = sqrtf(fmaf(rzB, rzB, fmaf(rxB, rxB, __fmul_rn(ryB, ryB)))) - rad;

        // ---- Relu-free MLP:  sum q*relu(h) = (u.p + v) + sum (q/2)*|h|
        const u64 pxxA = pack2(pxA, pxA), pyyA = pack2(pyA, pyA), pzzA = pack2(pzA, pzA);
        const u64 pxxB = pack2(pxB, pxB), pyyB = pack2(pyB, pyB), pzzB = pack2(pzB, pzB);
        u64 accA0 = 0ULL, accA1 = 0ULL, accB0 = 0ULL, accB1 = 0ULL;
        #pragma unroll 8
        for (int j = 0; j < HIDDEN / 2; j += 2) {
            {
                const ulonglong2 wxy = sW1v[2 * j];
                const ulonglong2 wzb = sW1v[2 * j + 1];
                const u64 qq = sQv[j];
                const u64 hA = ffma2(wxy.x, pxxA, ffma2(wxy.y, pyyA, ffma2(wzb.x, pzzA, wzb.y)));
                const u64 hB = ffma2(wxy.x, pxxB, ffma2(wxy.y, pyyB, ffma2(wzb.x, pzzB, wzb.y)));
                accA0 = ffma2(abs2(hA), qq, accA0);
                accB0 = ffma2(abs2(hB), qq, accB0);
            }
            {
                const ulonglong2 wxy = sW1v[2 * j + 2];
                const ulonglong2 wzb = sW1v[2 * j + 3];
                const u64 qq = sQv[j + 1];
                const u64 hA = ffma2(wxy.x, pxxA, ffma2(wxy.y, pyyA, ffma2(wzb.x, pzzA, wzb.y)));
                const u64 hB = ffma2(wxy.x, pxxB, ffma2(wxy.y, pyyB, ffma2(wzb.x, pzzB, wzb.y)));
                accA1 = ffma2(abs2(hA), qq, accA1);
                accB1 = ffma2(abs2(hB), qq, accB1);
            }
        }
        const float2 afA = unpack2(fadd2(accA0, accA1));
        const float2 afB = unpack2(fadd2(accB0, accB1));
        const float linA = fmaf(uv.x, pxA, fmaf(uv.y, pyA, fmaf(uv.z, pzA, uv.w)));
        const float linB = fmaf(uv.x, pxB, fmaf(uv.y, pyB, fmaf(uv.z, pzB, uv.w)));
        const float dA = baseA + PERT * tanh_fast(((afA.x + afA.y) + linA) + bb2);
        const float dB = baseB + PERT * tanh_fast(((afB.x + afB.y) + linB) + bb2);

        // ---- Exact reference mask semantics (FROZEN) + receding cutoff.
        {
            const bool curr_hit = fabsf(dA) < HIT_T;
            const bool missed   = distA > FAR_DIST;
            hitA = hitA || (unfA && curr_hit);
            const bool still = unfA && !curr_hit && !missed;
            if (still) {
                pxA = fmaf(dA, dxA, pxA);
                pyA = fmaf(dA, dyA, pyA);
                pzA = fmaf(dA, dzA, pzA);
                distA += dA;
            }
            const float dotA = rxA * dxA + ryA * dyA + rzA * dzA;
            unfA = still && !((baseA > KILL_MARGIN) && (dotA >= 0.0f));
        }
        {
            const bool curr_hit = fabsf(dB) < HIT_T;
            const bool missed   = distB > FAR_DIST;
            hitB = hitB || (unfB && curr_hit);
            const bool still = unfB && !curr_hit && !missed;
            if (still) {
                pxB = fmaf(dB, dxB, pxB);
                pyB = fmaf(dB, dyB, pyB);
                pzB = fmaf(dB, dzB, pzB);
                distB += dB;
            }
            const float dotB = rxB * dxB + ryB * dyB + rzB * dzB;
            unfB = still && !((baseB > KILL_MARGIN) && (dotB >= 0.0f));
        }
    }

    // ---- Color MLP (packed, TRUE relu, warp-coherent post-sort).
    float rA = 0.0f, gA = 0.0f, bA = 0.0f;
    float rB = 0.0f, gB = 0.0f, bB = 0.0f;
    if (hitA || hitB) {
        const u64 pxxA = pack2(pxA, pxA), pyyA = pack2(pyA, pyA), pzzA = pack2(pzA, pzA);
        const u64 pxxB = pack2(pxB, pxB), pyyB = pack2(pyB, pyB), pzzB = pack2(pzB, pzB);
        u64 c0A = 0ULL, c1A = 0ULL, c2A = 0ULL;
        u64 c0B = 0ULL, c1B = 0ULL, c2B = 0ULL;
        #pragma unroll 4
        for (int j = 0; j < HIDDEN / 2; ++j) {
            const ulonglong2 wxy = sC1v[2 * j];
            const ulonglong2 wzb = sC1v[2 * j + 1];
            const ulonglong2 vxy = sC2xy[j];
            const u64 vz = sC2z[j];
            const u64 hA = relu2(ffma2(wxy.x, pxxA, ffma2(wxy.y, pyyA, ffma2(wzb.x, pzzA, wzb.y))));
            const u64 hB = relu2(ffma2(wxy.x, pxxB, ffma2(wxy.y, pyyB, ffma2(wzb.x, pzzB, wzb.y))));
            c0A = ffma2(hA, vxy.x, c0A);  c0B = ffma2(hB, vxy.x, c0B);
            c1A = ffma2(hA, vxy.y, c1A);  c1B = ffma2(hB, vxy.y, c1B);
            c2A = ffma2(hA, vz,    c2A);  c2B = ffma2(hB, vz,    c2B);
        }
        if (hitA) {
            const float2 f0 = unpack2(c0A), f1 = unpack2(c1A), f2 = unpack2(c2A);
            rA = 1.0f / (1.0f + __expf(-((f0.x + f0.y) + bo0)));
            gA = 1.0f / (1.0f + __expf(-((f1.x + f1.y) + bo1)));
            bA = 1.0f / (1.0f + __expf(-((f2.x + f2.y) + bo2)));
        }
        if (hitB) {
            const float2 f0 = unpack2(c0B), f1 = unpack2(c1B), f2 = unpack2(c2B);
            rB = 1.0f / (1.0f + __expf(-((f0.x + f0.y) + bo0)));
            gB = 1.0f / (1.0f + __expf(-((f1.x + f1.y) + bo1)));
            bB = 1.0f / (1.0f + __expf(-((f2.x + f2.y) + bo2)));
        }
    }
    out[3 * rayA + 0] = rA;
    out[3 * rayA + 1] = gA;
    out[3 * rayA + 2] = bA;
    out[3 * rayB + 0] = rB;
    out[3 * rayB + 1] = gB;
    out[3 * rayB + 2] = bB;
}

extern "C" void kernel_launch(void* const* d_in, const int* in_sizes, int n_in,
                              void* d_out, int out_size)
{
    const float* origins    = (const float*)d_in[0];
    const float* directions = (const float*)d_in[1];
    const float* center     = (const float*)d_in[2];
    const float* radius     = (const float*)d_in[3];
    const float* W1         = (const float*)d_in[4];
    const float* b1         = (const float*)d_in[5];
    const float* W2         = (const float*)d_in[6];
    const float* b2         = (const float*)d_in[7];
    const float* Wc1        = (const float*)d_in[8];
    const float* bc1        = (const float*)d_in[9];
    const float* Wc2        = (const float*)d_in[10];
    const float* bc2        = (const float*)d_in[11];
    float* out = (float*)d_out;

    // Cheap-proxy counting sort + skip flags + u,v precompute.
    key_blockhist_kernel<<<NBLK, 256>>>(origins, directions, center, radius);
    bucket_scan_kernel<<<NBKT, NBLK>>>();
    total_scan_kernel<<<1, NBKT>>>(W1, b1, W2);
    scatter_kernel<<<NBLK, 256>>>();

    const int blocks = N_RAYS / (THREADS * RPT);  // 1024
    sphere_trace_render_kernel<<<blocks, THREADS>>>(
        origins, directions, center, radius,
        W1, b1, W2, b2, Wc1, bc1, Wc2, bc2, out);
}

// round 17
// speedup vs baseline: 1.1002x; 1.1002x over previous
#include <cuda_runtime.h>
#include <math.h>

#define N_RAYS   262144
#define HIDDEN   256
#define MAX_ITERS 32
#define FAR_DIST 6.0f
#define HIT_T    1e-5f
#define PERT     1e-3f
#define THREADS  128
#define RPT      2
#define NBKT     256
#define NBLK     (N_RAYS / 256)             // 1024 key blocks
#define NWARPS_TOT (N_RAYS / (32 * RPT))    // 4096 trace warps
#define SKIP_BKT 255
#define KILL_MARGIN 2.5e-3f                 // > PERT + HIT_T + fp slop

typedef unsigned long long u64;

// ---- packed f32x2 helpers (sm_103a) ----
__device__ __forceinline__ u64 ffma2(u64 a, u64 b, u64 c) {
    u64 d;
    asm("fma.rn.f32x2 %0, %1, %2, %3;" : "=l"(d) : "l"(a), "l"(b), "l"(c));
    return d;
}
__device__ __forceinline__ u64 fadd2(u64 a, u64 b) {
    u64 d;
    asm("add.rn.f32x2 %0, %1, %2;" : "=l"(d) : "l"(a), "l"(b));
    return d;
}
__device__ __forceinline__ u64 pack2(float lo, float hi) {
    u64 r;
    asm("mov.b64 %0, {%1, %2};" : "=l"(r) : "f"(lo), "f"(hi));
    return r;
}
__device__ __forceinline__ float2 unpack2(u64 v) {
    float2 r;
    asm("mov.b64 {%0, %1}, %2;" : "=f"(r.x), "=f"(r.y) : "l"(v));
    return r;
}
__device__ __forceinline__ u64 relu2(u64 h) {
    float2 f = unpack2(h);
    return pack2(fmaxf(f.x, 0.0f), fmaxf(f.y, 0.0f));
}
// packed |.|: clear both sign bits (2 LOP3, or folded into FFMA2 |src|)
__device__ __forceinline__ u64 abs2(u64 h) {
    return h & 0x7FFFFFFF7FFFFFFFULL;
}
// tanh with ~1e-6 abs error (damped x1e-3 -> ~1e-9 in d)
__device__ __forceinline__ float tanh_fast(float x) {
    const float e = __expf(2.0f * x);
    return 1.0f - __fdividef(2.0f, e + 1.0f);
}

// ---- sorting scratch + precomputed u,v (allocation-free: device globals) ----
__device__ int g_bucket[N_RAYS];
__device__ int g_perm[N_RAYS];
__device__ int g_blockhist[NBLK * NBKT];
__device__ int g_blockbase[NBKT * NBLK];
__device__ int g_tot[NBKT];
__device__ int g_bucketbase[NBKT];
__device__ float4 g_uv;   // u = 0.5*sum q_i w_i (xyz), v = 0.5*sum q_i b_i (w)

// ---- Phase 1: iteration-exact key via sim trace WITH the receding cutoff;
// ----          conservative provably-never-hit skip flag.
__global__ void key_blockhist_kernel(const float* __restrict__ origins,
                                     const float* __restrict__ directions,
                                     const float* __restrict__ center,
                                     const float* __restrict__ radius)
{
    __shared__ int s_hist[NBKT];
    const int t = threadIdx.x;
    s_hist[t] = 0;
    __syncthreads();

    const int r = blockIdx.x * 256 + t;
    const float ox = origins[3 * r + 0] - center[0];
    const float oy = origins[3 * r + 1] - center[1];
    const float oz = origins[3 * r + 2] - center[2];
    const float dx = directions[3 * r + 0];
    const float dy = directions[3 * r + 1];
    const float dz = directions[3 * r + 2];
    const float rad = radius[0];

    // Never-hit at birth: tca = dot(o-c,d); forward closest approach iff tca<0.
    const float tca = ox * dx + oy * dy + oz * dz;
    const float oc2 = ox * ox + oy * oy + oz * oz;
    const float b   = sqrtf(fmaxf(oc2 - tca * tca, 0.0f));
    const float minD = (tca < 0.0f) ? b : sqrtf(oc2);
    const bool skip = (minD - rad) > 2e-3f;

    int bkt;
    if (skip) {
        bkt = SKIP_BKT;
    } else {
        // simulate unperturbed trace with the same receding cutoff (key only)
        float tt = 0.0f;
        int k = 0;
        bool simhit = false;
        #pragma unroll 1
        for (k = 0; k < MAX_ITERS; ++k) {
            const float x = ox + tt * dx, y = oy + tt * dy, z = oz + tt * dz;
            const float ds = sqrtf(x * x + y * y + z * z) - rad;
            if (ds < 2e-3f) { simhit = true; break; }
            const float dt = x * dx + y * dy + z * dz;
            if (dt >= 0.0f && ds > KILL_MARGIN) break;   // receding cutoff
            if (tt > FAR_DIST) break;
            tt += ds;
        }
        bkt = simhit ? k : (64 + k);          // hits 0..31, misses 64..96
    }
    g_bucket[r] = bkt;
    atomicAdd(&s_hist[bkt], 1);
    __syncthreads();
    g_blockhist[blockIdx.x * NBKT + t] = s_hist[t];
}

__global__ void bucket_scan_kernel()
{
    __shared__ int s[NBLK];
    const int bucket = blockIdx.x;
    const int t = threadIdx.x;
    const int c = g_blockhist[t * NBKT + bucket];
    s[t] = c;
    __syncthreads();
    #pragma unroll
    for (int off = 1; off < NBLK; off <<= 1) {
        const int v = (t >= off) ? s[t - off] : 0;
        __syncthreads();
        s[t] += v;
        __syncthreads();
    }
    g_blockbase[bucket * NBLK + t] = s[t] - c;
    if (t == NBLK - 1) g_tot[bucket] = s[t];
}

// Phase 3: scan of bucket totals + deterministic u,v reduction.
__global__ void total_scan_kernel(const float* __restrict__ W1,
                                  const float* __restrict__ b1,
                                  const float* __restrict__ W2)
{
    __shared__ int s[NBKT];
    __shared__ float4 red[NBKT];
    const int t = threadIdx.x;
    const int h = g_tot[t];
    s[t] = h;
    const float qh = 0.5f * W2[t];
    red[t] = make_float4(qh * W1[t], qh * W1[HIDDEN + t],
                         qh * W1[2 * HIDDEN + t], qh * b1[t]);
    __syncthreads();
    #pragma unroll
    for (int off = 1; off < NBKT; off <<= 1) {
        const int v = (t >= off) ? s[t - off] : 0;
        __syncthreads();
        s[t] += v;
        __syncthreads();
    }
    g_bucketbase[t] = s[t] - h;
    // deterministic tree reduce for u,v
    #pragma unroll
    for (int off = NBKT / 2; off >= 1; off >>= 1) {
        if (t < off) {
            float4 a = red[t], bb = red[t + off];
            red[t] = make_float4(a.x + bb.x, a.y + bb.y, a.z + bb.z, a.w + bb.w);
        }
        __syncthreads();
    }
    if (t == 0) g_uv = red[0];
}

__global__ void scatter_kernel()
{
    __shared__ int s_base[NBKT];
    __shared__ int s_cnt[NBKT];
    const int t = threadIdx.x;
    s_base[t] = g_bucketbase[t] + g_blockbase[t * NBLK + blockIdx.x];
    s_cnt[t] = 0;
    __syncthreads();
    const int r = blockIdx.x * 256 + t;
    const int bkt = g_bucket[r];
    const int lr = atomicAdd(&s_cnt[bkt], 1);
    g_perm[s_base[bkt] + lr] = r;
}

// ---- main trace kernel: unit-pair packed f32x2 MLP, relu-free layer 2 ----
__global__ __launch_bounds__(THREADS)
void sphere_trace_render_kernel(const float* __restrict__ origins,
                                const float* __restrict__ directions,
                                const float* __restrict__ center,
                                const float* __restrict__ radius,
                                const float* __restrict__ W1,
                                const float* __restrict__ b1,
                                const float* __restrict__ W2,
                                const float* __restrict__ b2,
                                const float* __restrict__ Wc1,
                                const float* __restrict__ bc1,
                                const float* __restrict__ Wc2,
                                const float* __restrict__ bc2,
                                float* __restrict__ out)
{
    // Pair-packed weights: pair j = units (2j, 2j+1).
    __shared__ ulonglong2 sW1v[HIDDEN];
    __shared__ u64        sQv[HIDDEN / 2];     // (q_e/2, q_o/2)
    __shared__ ulonglong2 sC1v[HIDDEN];
    __shared__ ulonglong2 sC2xy[HIDDEN / 2];
    __shared__ u64        sC2z[HIDDEN / 2];

    const int t = threadIdx.x;
    for (int i = t; i < HIDDEN; i += THREADS) {
        const int j = i >> 1;
        float4 v;
        if ((i & 1) == 0)
            v = make_float4(W1[2 * j], W1[2 * j + 1], W1[HIDDEN + 2 * j], W1[HIDDEN + 2 * j + 1]);
        else
            v = make_float4(W1[2 * HIDDEN + 2 * j], W1[2 * HIDDEN + 2 * j + 1], b1[2 * j], b1[2 * j + 1]);
        ((float4*)sW1v)[i] = v;
        if ((i & 1) == 0)
            v = make_float4(Wc1[2 * j], Wc1[2 * j + 1], Wc1[HIDDEN + 2 * j], Wc1[HIDDEN + 2 * j + 1]);
        else
            v = make_float4(Wc1[2 * HIDDEN + 2 * j], Wc1[2 * HIDDEN + 2 * j + 1], bc1[2 * j], bc1[2 * j + 1]);
        ((float4*)sC1v)[i] = v;
    }
    for (int i = t; i < HIDDEN / 2; i += THREADS) {
        ((float2*)sQv)[i] = make_float2(0.5f * W2[2 * i], 0.5f * W2[2 * i + 1]);
        ((float4*)sC2xy)[i] = make_float4(Wc2[3 * (2 * i)],     Wc2[3 * (2 * i + 1)],
                                          Wc2[3 * (2 * i) + 1], Wc2[3 * (2 * i + 1) + 1]);
        ((float2*)sC2z)[i]  = make_float2(Wc2[3 * (2 * i) + 2], Wc2[3 * (2 * i + 1) + 2]);
    }
    __syncthreads();

    // Warp -> sorted segment, hard/easy folded for SM load balance.
    const int w = t >> 5, lane = t & 31;
    const int g = blockIdx.x * (THREADS / 32) + w;                 // 0..4095
    const int s = (g & 1) ? (NWARPS_TOT - 1 - (g >> 1)) : (g >> 1);
    const int base = s * (32 * RPT) + lane;

    const int rayA = g_perm[base];
    const int rayB = g_perm[base + 32];

    float pxA = origins[3 * rayA + 0], pyA = origins[3 * rayA + 1], pzA = origins[3 * rayA + 2];
    float pxB = origins[3 * rayB + 0], pyB = origins[3 * rayB + 1], pzB = origins[3 * rayB + 2];
    const float dxA = directions[3 * rayA + 0], dyA = directions[3 * rayA + 1], dzA = directions[3 * rayA + 2];
    const float dxB = directions[3 * rayB + 0], dyB = directions[3 * rayB + 1], dzB = directions[3 * rayB + 2];

    const float cx  = center[0];
    const float cy  = center[1];
    const float cz  = center[2];
    const float rad = radius[0];
    const float bb2 = b2[0];
    const float bo0 = bc2[0];
    const float bo1 = bc2[1];
    const float bo2 = bc2[2];
    const float4 uv = g_uv;     // u (xyz), v (w): linear half of relu split

    float distA = 0.0f, distB = 0.0f;
    bool  unfA = (g_bucket[rayA] != SKIP_BKT);
    bool  unfB = (g_bucket[rayB] != SKIP_BKT);
    bool  hitA = false, hitB = false;

    for (int it = 0; it < MAX_ITERS; ++it) {
        if (__all_sync(0xFFFFFFFFu, !unfA && !unfB)) break;

        // ---- Geometry (FROZEN form): norm = fma(rz,rz, fma(rx,rx, ry*ry))
        const float rxA = pxA - cx, ryA = pyA - cy, rzA = pzA - cz;
        const float baseA = sqrtf(fmaf(rzA, rzA, fmaf(rxA, rxA, __fmul_rn(ryA, ryA)))) - rad;
        const float rxB = pxB - cx, ryB = pyB - cy, rzB = pzB - cz;
        const float baseB = sqrtf(fmaf(rzB, rzB, fmaf(rxB, rxB, __fmul_rn(ryB, ryB)))) - rad;

        // ---- Relu-free MLP:  sum q*relu(h) = (u.p + v) + sum (q/2)*|h|
        const u64 pxxA = pack2(pxA, pxA), pyyA = pack2(pyA, pyA), pzzA = pack2(pzA, pzA);
        const u64 pxxB = pack2(pxB, pxB), pyyB = pack2(pyB, pyB), pzzB = pack2(pzB, pzB);
        u64 accA0 = 0ULL, accA1 = 0ULL, accB0 = 0ULL, accB1 = 0ULL;
        #pragma unroll 8
        for (int j = 0; j < HIDDEN / 2; j += 2) {
            {
                const ulonglong2 wxy = sW1v[2 * j];
                const ulonglong2 wzb = sW1v[2 * j + 1];
                const u64 qq = sQv[j];
                const u64 hA = ffma2(wxy.x, pxxA, ffma2(wxy.y, pyyA, ffma2(wzb.x, pzzA, wzb.y)));
                const u64 hB = ffma2(wxy.x, pxxB, ffma2(wxy.y, pyyB, ffma2(wzb.x, pzzB, wzb.y)));
                accA0 = ffma2(abs2(hA), qq, accA0);
                accB0 = ffma2(abs2(hB), qq, accB0);
            }
            {
                const ulonglong2 wxy = sW1v[2 * j + 2];
                const ulonglong2 wzb = sW1v[2 * j + 3];
                const u64 qq = sQv[j + 1];
                const u64 hA = ffma2(wxy.x, pxxA, ffma2(wxy.y, pyyA, ffma2(wzb.x, pzzA, wzb.y)));
                const u64 hB = ffma2(wxy.x, pxxB, ffma2(wxy.y, pyyB, ffma2(wzb.x, pzzB, wzb.y)));
                accA1 = ffma2(abs2(hA), qq, accA1);
                accB1 = ffma2(abs2(hB), qq, accB1);
            }
        }
        const float2 afA = unpack2(fadd2(accA0, accA1));
        const float2 afB = unpack2(fadd2(accB0, accB1));
        const float linA = fmaf(uv.x, pxA, fmaf(uv.y, pyA, fmaf(uv.z, pzA, uv.w)));
        const float linB = fmaf(uv.x, pxB, fmaf(uv.y, pyB, fmaf(uv.z, pzB, uv.w)));
        const float dA = baseA + PERT * tanh_fast(((afA.x + afA.y) + linA) + bb2);
        const float dB = baseB + PERT * tanh_fast(((afB.x + afB.y) + linB) + bb2);

        // ---- Exact reference mask semantics (FROZEN) + receding cutoff.
        {
            const bool curr_hit = fabsf(dA) < HIT_T;
            const bool missed   = distA > FAR_DIST;
            hitA = hitA || (unfA && curr_hit);
            const bool still = unfA && !curr_hit && !missed;
            if (still) {
                pxA = fmaf(dA, dxA, pxA);
                pyA = fmaf(dA, dyA, pyA);
                pzA = fmaf(dA, dzA, pzA);
                distA += dA;
            }
            const float dotA = rxA * dxA + ryA * dyA + rzA * dzA;
            unfA = still && !((baseA > KILL_MARGIN) && (dotA >= 0.0f));
        }
        {
            const bool curr_hit = fabsf(dB) < HIT_T;
            const bool missed   = distB > FAR_DIST;
            hitB = hitB || (unfB && curr_hit);
            const bool still = unfB && !curr_hit && !missed;
            if (still) {
                pxB = fmaf(dB, dxB, pxB);
                pyB = fmaf(dB, dyB, pyB);
                pzB = fmaf(dB, dzB, pzB);
                distB += dB;
            }
            const float dotB = rxB * dxB + ryB * dyB + rzB * dzB;
            unfB = still && !((baseB > KILL_MARGIN) && (dotB >= 0.0f));
        }
    }

    // ---- Color MLP (packed, TRUE relu, warp-coherent post-sort).
    float rA = 0.0f, gA = 0.0f, bA = 0.0f;
    float rB = 0.0f, gB = 0.0f, bB = 0.0f;
    if (hitA || hitB) {
        const u64 pxxA = pack2(pxA, pxA), pyyA = pack2(pyA, pyA), pzzA = pack2(pzA, pzA);
        const u64 pxxB = pack2(pxB, pxB), pyyB = pack2(pyB, pyB), pzzB = pack2(pzB, pzB);
        u64 c0A = 0ULL, c1A = 0ULL, c2A = 0ULL;
        u64 c0B = 0ULL, c1B = 0ULL, c2B = 0ULL;
        #pragma unroll 4
        for (int j = 0; j < HIDDEN / 2; ++j) {
            const ulonglong2 wxy = sC1v[2 * j];
            const ulonglong2 wzb = sC1v[2 * j + 1];
            const ulonglong2 vxy = sC2xy[j];
            const u64 vz = sC2z[j];
            const u64 hA = relu2(ffma2(wxy.x, pxxA, ffma2(wxy.y, pyyA, ffma2(wzb.x, pzzA, wzb.y))));
            const u64 hB = relu2(ffma2(wxy.x, pxxB, ffma2(wxy.y, pyyB, ffma2(wzb.x, pzzB, wzb.y))));
            c0A = ffma2(hA, vxy.x, c0A);  c0B = ffma2(hB, vxy.x, c0B);
            c1A = ffma2(hA, vxy.y, c1A);  c1B = ffma2(hB, vxy.y, c1B);
            c2A = ffma2(hA, vz,    c2A);  c2B = ffma2(hB, vz,    c2B);
        }
        if (hitA) {
            const float2 f0 = unpack2(c0A), f1 = unpack2(c1A), f2 = unpack2(c2A);
            rA = 1.0f / (1.0f + __expf(-((f0.x + f0.y) + bo0)));
            gA = 1.0f / (1.0f + __expf(-((f1.x + f1.y) + bo1)));
            bA = 1.0f / (1.0f + __expf(-((f2.x + f2.y) + bo2)));
        }
        if (hitB) {
            const float2 f0 = unpack2(c0B), f1 = unpack2(c1B), f2 = unpack2(c2B);
            rB = 1.0f / (1.0f + __expf(-((f0.x + f0.y) + bo0)));
            gB = 1.0f / (1.0f + __expf(-((f1.x + f1.y) + bo1)));
            bB = 1.0f / (1.0f + __expf(-((f2.x + f2.y) + bo2)));
        }
    }
    out[3 * rayA + 0] = rA;
    out[3 * rayA + 1] = gA;
    out[3 * rayA + 2] = bA;
    out[3 * rayB + 0] = rB;
    out[3 * rayB + 1] = gB;
    out[3 * rayB + 2] = bB;
}

extern "C" void kernel_launch(void* const* d_in, const int* in_sizes, int n_in,
                              void* d_out, int out_size)
{
    const float* origins    = (const float*)d_in[0];
    const float* directions = (const float*)d_in[1];
    const float* center     = (const float*)d_in[2];
    const float* radius     = (const float*)d_in[3];
    const float* W1         = (const float*)d_in[4];
    const float* b1         = (const float*)d_in[5];
    const float* W2         = (const float*)d_in[6];
    const float* b2         = (const float*)d_in[7];
    const float* Wc1        = (const float*)d_in[8];
    const float* bc1        = (const float*)d_in[9];
    const float* Wc2        = (const float*)d_in[10];
    const float* bc2        = (const float*)d_in[11];
    float* out = (float*)d_out;

    // Cutoff-aware counting sort + skip flags + u,v precompute.
    key_blockhist_kernel<<<NBLK, 256>>>(origins, directions, center, radius);
    bucket_scan_kernel<<<NBKT, NBLK>>>();
    total_scan_kernel<<<1, NBKT>>>(W1, b1, W2);
    scatter_kernel<<<NBLK, 256>>>();

    const int blocks = N_RAYS / (THREADS * RPT);  // 1024
    sphere_trace_render_kernel<<<blocks, THREADS>>>(
        origins, directions, center, radius,
        W1, b1, W2, b2, Wc1, bc1, Wc2, bc2, out);
}